// round 17
// baseline (speedup 1.0000x reference)
#include <cuda_runtime.h>
#include <cuda_bf16.h>
#include <stdint.h>
#include <math.h>

#define NN 10000        // nodes
#define EE 320000       // raw edges
#define ET 330000       // edges + self loops
#define FDIM 512        // H*C for all layers
#define SLOPE 0.2f

// ---------------- scratch (static device globals) ----------------------------
__device__ float          g_feat[NN * FDIM];   // fp32 activations (GEMM A input)
__device__ __nv_bfloat16  g_hb  [NN * FDIM];   // h buffer bf16 (gather side)
__device__ float          g_als [NN * 4];
__device__ float          g_ald [NN * 4];
__device__ float          g_alsP[4 * NN];      // per-colblock partials (H=1)
__device__ float          g_aldP[4 * NN];
__device__ int            g_off [NN + 1];
__device__ int            g_pos [NN];
__device__ int            g_csrc[ET];

// ======================= CSR build ===========================================
__global__ void zero_counts(int* cnt) {
    int i = blockIdx.x * blockDim.x + threadIdx.x;
    if (i < NN) cnt[i] = 0;
}

__global__ void count_deg(const int* __restrict__ ei, int* __restrict__ cnt) {
    int e = blockIdx.x * blockDim.x + threadIdx.x;
    if (e >= ET) return;
    int d = (e < EE) ? ei[EE + e] : (e - EE);
    atomicAdd(&cnt[d], 1);
}

#define SCHUNK 10   // 1024 * 10 >= NN
__global__ void scan_kernel(const int* __restrict__ cnt,
                            int* __restrict__ off, int* __restrict__ pos) {
    __shared__ int part[1024];
    int t = threadIdx.x;
    int base = t * SCHUNK;
    int local[SCHUNK];
    int s = 0;
    #pragma unroll
    for (int i = 0; i < SCHUNK; i++) {
        int idx = base + i;
        local[i] = s;
        s += (idx < NN) ? cnt[idx] : 0;
    }
    part[t] = s;
    __syncthreads();
    for (int o = 1; o < 1024; o <<= 1) {
        int v = (t >= o) ? part[t - o] : 0;
        __syncthreads();
        part[t] += v;
        __syncthreads();
    }
    int prev = (t > 0) ? part[t - 1] : 0;
    #pragma unroll
    for (int i = 0; i < SCHUNK; i++) {
        int idx = base + i;
        if (idx < NN) {
            int o = prev + local[i];
            off[idx] = o;
            pos[idx] = o;
        }
    }
    if (t == 1023) off[NN] = part[1023];
}

__global__ void scatter_edges(const int* __restrict__ ei,
                              int* __restrict__ pos, int* __restrict__ csrc) {
    int e = blockIdx.x * blockDim.x + threadIdx.x;
    if (e >= ET) return;
    int s, d;
    if (e < EE) { s = ei[e]; d = ei[EE + e]; } else { s = d = e - EE; }
    int p = atomicAdd(&pos[d], 1);
    csrc[p] = s;
}

// ======================= combine per-colblock attn partials (H=1) ============
__global__ void combine_attn(const float* __restrict__ alsP,
                             const float* __restrict__ aldP,
                             float* __restrict__ als, float* __restrict__ ald) {
    int i = blockIdx.x * blockDim.x + threadIdx.x;
    if (i >= NN) return;
    als[i] = alsP[i] + alsP[NN + i] + alsP[2 * NN + i] + alsP[3 * NN + i];
    ald[i] = aldP[i] + aldP[NN + i] + aldP[2 * NN + i] + aldP[3 * NN + i];
}

// ======================= tf32 GEMM (BM=64, vectorized fragment smem) =========
// Fragments stored pre-converted to tf32 in mma-native permuted layouts:
//   A: float4 per (g=row16grp, ko=k-oct, gid, tig); padded stride 5 float4.
//      comp c = rowhalf + 2*khalf, so one LDS.128 = one mma A fragment.
//   B: float2 per (c, ko, tig) = (B[c][ko*8+tig], B[c][ko*8+tig+4]); stride 9
//      float2 per c. One LDS.64 = one mma B fragment.
__device__ __forceinline__ uint32_t f2tf(float f) {
    uint32_t r; asm("cvt.rna.tf32.f32 %0, %1;" : "=r"(r) : "f"(f)); return r;
}

__device__ __forceinline__ void mma8(float* d, const uint32_t* a, const uint32_t* b) {
    asm volatile("mma.sync.aligned.m16n8k8.row.col.f32.tf32.tf32.f32 "
                 "{%0,%1,%2,%3},{%4,%5,%6,%7},{%8,%9},{%0,%1,%2,%3};"
                 : "+f"(d[0]), "+f"(d[1]), "+f"(d[2]), "+f"(d[3])
                 : "r"(a[0]), "r"(a[1]), "r"(a[2]), "r"(a[3]),
                   "r"(b[0]), "r"(b[1]));
}

__global__ __launch_bounds__(256, 3)
void tf32gemm(const float* __restrict__ A, const float* __restrict__ W,
              __nv_bfloat16* __restrict__ C, int n, int K,
              const float* __restrict__ a_src, const float* __restrict__ a_dst,
              float* __restrict__ als, float* __restrict__ ald,
              float* __restrict__ alsP, float* __restrict__ aldP, int H) {
    __shared__ uint32_t AsS[2][1280];   // 4g x 2ko x 8gid x (5 float4 pad)
    __shared__ uint32_t BsS[2][2304];   // 128c x (9 float2 pad)
    __shared__ float sRed[4][64][2];

    int tid = threadIdx.x;
    int wid = tid >> 5, lane = tid & 31;
    int gid = lane >> 2, tig = lane & 3;
    int mH = wid & 1;                  // row half (rows mH*32 .. +31)
    int nW = (wid >> 1) * 32;          // warp n offset
    int nWg = wid >> 1;
    int rowBase = blockIdx.y * 64;
    int colBase = blockIdx.x * 128;

    float acc[2][4][4] = {};
    int nk = K >> 4;

    // ---- loader geometry ----
    // A: thread -> row a_r, k quad a_ks (4 consecutive k)
    int a_r = tid >> 2, a_ks = (tid & 3) * 4;
    int a_grow = rowBase + a_r;
    int a_ko = a_ks >> 3;
    int a_comp = ((a_r >> 3) & 1) + 2 * ((a_ks >> 2) & 1);
    int a_base = (((a_r >> 4) * 2 + a_ko) * 8 + (a_r & 7)) * 20 + a_comp;
    // B: thread -> column b_c, k oct b_ko (8 strided k)
    int b_c = tid & 127, b_ko = tid >> 7;
    int b_base = (b_c * 9 + b_ko * 4) * 2;

    float4 aReg;
    float  bReg[8];

    auto ldg_tile = [&](int k0) {
        aReg = (a_grow < n)
             ? *(const float4*)(A + (size_t)a_grow * K + k0 + a_ks)
             : make_float4(0.f, 0.f, 0.f, 0.f);
        const float* wp = W + (size_t)(k0 + b_ko * 8) * FDIM + colBase + b_c;
        #pragma unroll
        for (int kr = 0; kr < 8; kr++) bReg[kr] = wp[kr * FDIM];
    };

    auto sts_tile = [&](int buf) {
        AsS[buf][a_base +  0] = f2tf(aReg.x);
        AsS[buf][a_base +  4] = f2tf(aReg.y);
        AsS[buf][a_base +  8] = f2tf(aReg.z);
        AsS[buf][a_base + 12] = f2tf(aReg.w);
        #pragma unroll
        for (int tg = 0; tg < 4; tg++) {
            uint2 v = make_uint2(f2tf(bReg[tg]), f2tf(bReg[tg + 4]));
            *(uint2*)&BsS[buf][b_base + tg * 2] = v;
        }
    };

    auto compute = [&](int cur) {
        #pragma unroll
        for (int kk2 = 0; kk2 < 2; kk2++) {
            uint4 af[2]; uint2 bf[4];
            #pragma unroll
            for (int i = 0; i < 2; i++) {
                int gA = mH * 2 + i;
                af[i] = *(const uint4*)&AsS[cur][((gA * 2 + kk2) * 8 + gid) * 20 + tig * 4];
            }
            #pragma unroll
            for (int j = 0; j < 4; j++) {
                int c = nW + j * 8 + gid;
                bf[j] = *(const uint2*)&BsS[cur][(c * 9 + kk2 * 4 + tig) * 2];
            }
            #pragma unroll
            for (int i = 0; i < 2; i++)
                #pragma unroll
                for (int j = 0; j < 4; j++)
                    mma8(acc[i][j], (const uint32_t*)&af[i], (const uint32_t*)&bf[j]);
        }
    };

    // ---- pipeline: LDG -> regs -> permuted STS, double buffered ----
    ldg_tile(0);
    sts_tile(0);
    if (nk > 1) ldg_tile(16);
    __syncthreads();

    for (int kt = 0; kt < nk; kt++) {
        int cur = kt & 1;
        if (kt + 1 < nk) {
            sts_tile(cur ^ 1);
            if (kt + 2 < nk) ldg_tile((kt + 2) << 4);
        }
        compute(cur);
        __syncthreads();
    }

    // ---- epilogue: bf16 stores + fused attention dot-products ----
    int mW = mH * 32;
    int head = (colBase * H) / FDIM;
    #pragma unroll
    for (int i = 0; i < 2; i++) {
        int r0 = rowBase + mW + i * 16 + gid;
        int r1 = r0 + 8;
        float s0 = 0.f, d0 = 0.f, s1 = 0.f, d1 = 0.f;
        #pragma unroll
        for (int j = 0; j < 4; j++) {
            int c = colBase + nW + j * 8 + tig * 2;
            float2 av = *(const float2*)(a_src + c);
            float2 dv = *(const float2*)(a_dst + c);
            if (r0 < n) *(__nv_bfloat162*)(C + (size_t)r0 * FDIM + c) =
                __float22bfloat162_rn(make_float2(acc[i][j][0], acc[i][j][1]));
            if (r1 < n) *(__nv_bfloat162*)(C + (size_t)r1 * FDIM + c) =
                __float22bfloat162_rn(make_float2(acc[i][j][2], acc[i][j][3]));
            s0 += acc[i][j][0] * av.x + acc[i][j][1] * av.y;
            d0 += acc[i][j][0] * dv.x + acc[i][j][1] * dv.y;
            s1 += acc[i][j][2] * av.x + acc[i][j][3] * av.y;
            d1 += acc[i][j][2] * dv.x + acc[i][j][3] * dv.y;
        }
        #pragma unroll
        for (int o = 1; o < 4; o <<= 1) {
            s0 += __shfl_xor_sync(0xffffffffu, s0, o);
            d0 += __shfl_xor_sync(0xffffffffu, d0, o);
            s1 += __shfl_xor_sync(0xffffffffu, s1, o);
            d1 += __shfl_xor_sync(0xffffffffu, d1, o);
        }
        if (tig == 0) {
            int lr = mW + i * 16 + gid;
            sRed[nWg][lr][0] = s0;     sRed[nWg][lr][1] = d0;
            sRed[nWg][lr + 8][0] = s1; sRed[nWg][lr + 8][1] = d1;
        }
    }
    __syncthreads();
    if (tid < 64) {
        float ssum = sRed[0][tid][0] + sRed[1][tid][0]
                   + sRed[2][tid][0] + sRed[3][tid][0];
        float dsum = sRed[0][tid][1] + sRed[1][tid][1]
                   + sRed[2][tid][1] + sRed[3][tid][1];
        int grow = rowBase + tid;
        if (grow < n) {
            if (H == 4) {
                als[grow * 4 + head] = ssum;
                ald[grow * 4 + head] = dsum;
            } else {
                alsP[blockIdx.x * NN + grow] = ssum;
                aldP[blockIdx.x * NN + grow] = dsum;
            }
        }
    }
}

// ======================= fused single-pass softmax + aggregation =============
// 1 warp per dst; 16 bf16 channels per lane (2x LDG.128 per edge); 8 dsts/block.
__device__ __forceinline__ float leaky(float l) {
    return (l > 0.f) ? l : SLOPE * l;
}

__device__ __forceinline__ void bf8_fma(float* acc, uint4 raw, float e) {
    float2 f0 = __bfloat1622float2(*(__nv_bfloat162*)&raw.x);
    float2 f1 = __bfloat1622float2(*(__nv_bfloat162*)&raw.y);
    float2 f2 = __bfloat1622float2(*(__nv_bfloat162*)&raw.z);
    float2 f3 = __bfloat1622float2(*(__nv_bfloat162*)&raw.w);
    acc[0] += f0.x * e; acc[1] += f0.y * e;
    acc[2] += f1.x * e; acc[3] += f1.y * e;
    acc[4] += f2.x * e; acc[5] += f2.y * e;
    acc[6] += f3.x * e; acc[7] += f3.y * e;
}

__global__ void gat_agg(const int* __restrict__ off, const int* __restrict__ csrc,
                        const __nv_bfloat16* __restrict__ h,
                        const float* __restrict__ als, const float* __restrict__ ald,
                        const float* __restrict__ bias,
                        float* __restrict__ out, int H, int C, int relu) {
    int dst  = blockIdx.x * 8 + (threadIdx.x >> 5);
    if (dst >= NN) return;
    int lane = threadIdx.x & 31;

    int ch0  = lane * 16;              // this lane's 16 channels
    int head = ch0 / C;                // C=128 -> lane/8, C=512 -> 0
    float ad = ald[dst * H + head];

    int beg = off[dst], end = off[dst + 1];

    float acc[16] = {};
    float sum = 0.f;
    const __nv_bfloat16* hc = h + ch0;

    int e = beg;
    for (; e + 2 <= end; e += 2) {
        int s0 = csrc[e], s1 = csrc[e + 1];
        float e0 = __expf(leaky(als[s0 * H + head] + ad));
        float e1 = __expf(leaky(als[s1 * H + head] + ad));
        const __nv_bfloat16* p0 = hc + (size_t)s0 * FDIM;
        const __nv_bfloat16* p1 = hc + (size_t)s1 * FDIM;
        uint4 r00 = *(const uint4*)p0;
        uint4 r01 = *(const uint4*)(p0 + 8);
        uint4 r10 = *(const uint4*)p1;
        uint4 r11 = *(const uint4*)(p1 + 8);
        sum += e0 + e1;
        bf8_fma(acc,     r00, e0); bf8_fma(acc + 8, r01, e0);
        bf8_fma(acc,     r10, e1); bf8_fma(acc + 8, r11, e1);
    }
    if (e < end) {
        int s = csrc[e];
        float e0 = __expf(leaky(als[s * H + head] + ad));
        const __nv_bfloat16* p = hc + (size_t)s * FDIM;
        uint4 r0 = *(const uint4*)p;
        uint4 r1 = *(const uint4*)(p + 8);
        sum += e0;
        bf8_fma(acc, r0, e0); bf8_fma(acc + 8, r1, e0);
    }

    float inv = 1.f / sum;
    float* op = out + (size_t)dst * FDIM + ch0;
    #pragma unroll
    for (int q = 0; q < 4; q++) {
        float4 bv = *(const float4*)(bias + ch0 + q * 4);
        float o0 = acc[q*4+0] * inv + bv.x;
        float o1 = acc[q*4+1] * inv + bv.y;
        float o2 = acc[q*4+2] * inv + bv.z;
        float o3 = acc[q*4+3] * inv + bv.w;
        if (relu) {
            o0 = fmaxf(o0, 0.f); o1 = fmaxf(o1, 0.f);
            o2 = fmaxf(o2, 0.f); o3 = fmaxf(o3, 0.f);
        }
        *(float4*)(op + q * 4) = make_float4(o0, o1, o2, o3);
    }
}

// ======================= host-side driver ====================================
extern "C" void kernel_launch(void* const* d_in, const int* in_sizes, int n_in,
                              void* d_out, int out_size) {
    const float* x   = (const float*)d_in[0];
    const int*   ei  = (const int*)  d_in[1];
    const float* W1  = (const float*)d_in[2];
    const float* as1 = (const float*)d_in[3];
    const float* ad1 = (const float*)d_in[4];
    const float* b1  = (const float*)d_in[5];
    const float* W2  = (const float*)d_in[6];
    const float* as2 = (const float*)d_in[7];
    const float* ad2 = (const float*)d_in[8];
    const float* b2  = (const float*)d_in[9];
    const float* W3  = (const float*)d_in[10];
    const float* as3 = (const float*)d_in[11];
    const float* ad3 = (const float*)d_in[12];
    const float* b3  = (const float*)d_in[13];
    float* out = (float*)d_out;

    float *feat, *als, *ald, *alsP, *aldP;
    __nv_bfloat16* hbuf;
    int *off, *pos, *csrc;
    cudaGetSymbolAddress((void**)&feat, g_feat);
    cudaGetSymbolAddress((void**)&hbuf, g_hb);
    cudaGetSymbolAddress((void**)&als,  g_als);
    cudaGetSymbolAddress((void**)&ald,  g_ald);
    cudaGetSymbolAddress((void**)&alsP, g_alsP);
    cudaGetSymbolAddress((void**)&aldP, g_aldP);
    cudaGetSymbolAddress((void**)&off,  g_off);
    cudaGetSymbolAddress((void**)&pos,  g_pos);
    cudaGetSymbolAddress((void**)&csrc, g_csrc);

    static cudaStream_t s2 = 0;
    static cudaEvent_t evFork = 0, evJoin = 0;
    if (!s2) {
        cudaStreamCreate(&s2);
        cudaEventCreateWithFlags(&evFork, cudaEventDisableTiming);
        cudaEventCreateWithFlags(&evJoin, cudaEventDisableTiming);
    }

    // ---- fork: CSR build on s2, overlapped with layer-1 GEMM ----
    cudaEventRecord(evFork, 0);
    cudaStreamWaitEvent(s2, evFork, 0);
    zero_counts  <<<(NN + 255) / 256, 256, 0, s2>>>(pos);
    count_deg    <<<(ET + 255) / 256, 256, 0, s2>>>(ei, pos);
    scan_kernel  <<<1, 1024, 0, s2>>>(pos, off, pos);
    scatter_edges<<<(ET + 255) / 256, 256, 0, s2>>>(ei, pos, csrc);
    cudaEventRecord(evJoin, s2);

    dim3 gg(4, (NN + 63) / 64);

    // ---- layer 1 (H=4): GEMM(+attn) ; join CSR ; agg ----
    tf32gemm<<<gg, 256>>>(x, W1, hbuf, NN, 128, as1, ad1, als, ald, alsP, aldP, 4);
    cudaStreamWaitEvent(0, evJoin, 0);
    gat_agg<<<NN / 8, 256>>>(off, csrc, hbuf, als, ald, b1, feat, 4, 128, 1);

    // ---- layer 2 (H=4) ----
    tf32gemm<<<gg, 256>>>(feat, W2, hbuf, NN, 512, as2, ad2, als, ald, alsP, aldP, 4);
    gat_agg<<<NN / 8, 256>>>(off, csrc, hbuf, als, ald, b2, feat, 4, 128, 1);

    // ---- layer 3 (H=1): GEMM -> combine partials -> agg ----
    tf32gemm<<<gg, 256>>>(feat, W3, hbuf, NN, 512, as3, ad3, als, ald, alsP, aldP, 1);
    combine_attn<<<(NN + 255) / 256, 256>>>(alsP, aldP, als, ald);
    gat_agg<<<NN / 8, 256>>>(off, csrc, hbuf, als, ald, b3, out, 1, 512, 0);
}